// round 14
// baseline (speedup 1.0000x reference)
#include <cuda_runtime.h>
#include <cuda_fp16.h>
#include <stdint.h>

// ---------------- problem constants ----------------
#define BB 32
#define CC 128
#define NN 16384
#define KK 64
#define TILE_N 64
#define STRIPES 4
#define NT ((NN / STRIPES) / TILE_N)   // 64 tiles per CTA
#define NTHREADS 768

// ---------------- smem layout ----------------
#define PX  72       // x tile pitch (elems); 144 B rows
#define PBX 144
#define PA  72
#define PBA 144
#define PL  68       // logits pitch (fp32)

#define XBUF(i)   ((uint32_t)(i) * 20736u)   // X ring (fp16 hi only), 3 deep
#define OFF_LOG0  62208u     // [64][68] fp32
#define OFF_LOG1  79616u
#define OFF_AWHI0 97024u     // [64][72] fp16
#define OFF_AWHI1 106240u
#define OFF_BIAS  115456u    // 64 fp32
#define OFF_RED   115712u    // 512 fp32 (4 quarters max + 4 quarters sum)
#define SMEM_BYTES 117760u

// ---------------- named barrier ids ----------------
#define XC(s)  (1 + (s))     // conv(t) done -> G1 may read X[t%3]
#define XFB(s) (4 + (s))     // G2(t) done  -> conv(t+3) may write X[t%3]
#define LG(p)  (7 + (p))     // G1(t) done  -> softmax may read LOG[t%2]
#define LF(p)  (9 + (p))     // softmax(t) read LOG -> G1(t+2) may write
#define AIDB(p) (11 + (p))   // softmax(t) done -> G2 may read AW[t%2]
#define AWF(p) (13 + (p))    // G2(t) read AW[t%2] -> softmax(t+2) may write
#define SBAR   15            // scalar-internal (256)

#define BARSYNC(id)    asm volatile("bar.sync %0, 512;"   :: "r"(id) : "memory")
#define BARARR(id)     asm volatile("bar.arrive %0, 512;" :: "r"(id) : "memory")
#define BARSYNC256(id) asm volatile("bar.sync %0, 256;"   :: "r"(id) : "memory")

// ---------------- scratch (deterministic split-K, no atomics) ---------------
__device__ float g_pv[(size_t)STRIPES * BB * KK * CC];
__device__ float g_pa[STRIPES * BB * KK];
__device__ float g_rss[BB * KK];

// ---------------- helpers ----------------
__device__ __forceinline__ uint32_t smem_u32(const void* p) {
    uint32_t a;
    asm("{ .reg .u64 t; cvta.to.shared.u64 t, %1; cvt.u32.u64 %0, t; }"
        : "=r"(a) : "l"(p));
    return a;
}
__device__ __forceinline__ void ldm4(uint32_t* r, uint32_t a) {
    asm volatile("ldmatrix.sync.aligned.m8n8.x4.shared.b16 {%0,%1,%2,%3}, [%4];"
                 : "=r"(r[0]), "=r"(r[1]), "=r"(r[2]), "=r"(r[3]) : "r"(a));
}
__device__ __forceinline__ void ldm4t(uint32_t* r, uint32_t a) {
    asm volatile("ldmatrix.sync.aligned.m8n8.x4.trans.shared.b16 {%0,%1,%2,%3}, [%4];"
                 : "=r"(r[0]), "=r"(r[1]), "=r"(r[2]), "=r"(r[3]) : "r"(a));
}
__device__ __forceinline__ void mma_f16(float* d, const uint32_t* a, const uint32_t* b2) {
    asm volatile("mma.sync.aligned.m16n8k16.row.col.f32.f16.f16.f32 "
                 "{%0,%1,%2,%3}, {%4,%5,%6,%7}, {%8,%9}, {%0,%1,%2,%3};"
                 : "+f"(d[0]), "+f"(d[1]), "+f"(d[2]), "+f"(d[3])
                 : "r"(a[0]), "r"(a[1]), "r"(a[2]), "r"(a[3]), "r"(b2[0]), "r"(b2[1]));
}

// fast exp for v <= 0: pure FFMA/ALU, rel err ~2.4e-6
__device__ __forceinline__ float fast_exp_neg(float v) {
    float t = v * 1.4426950408889634f;
    t = fmaxf(t, -30.0f);
    float r  = t + 12582912.0f;
    float fi = r - 12582912.0f;
    float f  = t - fi;
    float p  = 0.0013333558146428443f;
    p = fmaf(p, f, 0.009618129107628477f);
    p = fmaf(p, f, 0.05550410866482158f);
    p = fmaf(p, f, 0.2402265069591007f);
    p = fmaf(p, f, 0.6931471805599453f);
    p = fmaf(p, f, 1.0f);
    int ei = (int)fi;
    return __int_as_float(__float_as_int(p) + (ei << 23));
}

// ---------------- dataflow-pipelined fused kernel (8+8+8 warps) -------------
__global__ __launch_bounds__(NTHREADS, 1)
void nv_df_kernel(const float* __restrict__ x,
                  const float* __restrict__ conv_w,
                  const float* __restrict__ conv_b) {
    extern __shared__ char sm[];
    const uint32_t sb = smem_u32(sm);
    float* smf = (float*)sm;
    const int tid = threadIdx.x;
    const int lane = tid & 31;
    const int w = tid >> 5;
    const int b = blockIdx.y, stripe = blockIdx.x;

    // ---- init: bias + ones rows in all 3 X buffers ----
    if (tid < KK) smf[(OFF_BIAS >> 2) + tid] = conv_b[tid];
    for (int i = tid; i < 16 * PX; i += NTHREADS) {   // rows 128..143
        int r = 128 + i / PX, c = i % PX;
        uint16_t hv = (r == 128) ? (uint16_t)0x3C00 : (uint16_t)0;   // fp16 1.0
        uint32_t o = (uint32_t)(r * PX + c) * 2;
        #pragma unroll
        for (int bu = 0; bu < 3; ++bu)
            *(uint16_t*)(sm + XBUF(bu) + o) = hv;
    }
    __syncthreads();

    const float* xb = x + (size_t)b * CC * NN;
    const int nbase = stripe * (NN / STRIPES);

    if (w < 8) {
        // ====== G1 group (warps 0-7): logits = Whi @ x_hi ======
        const int kq = w >> 1;         // k-slice (4 x 16 rows)
        const int nq = w & 1;          // n-half
        const int krow0 = kq * 16;
        uint32_t Whi[8][4];
        {
            const int r0 = krow0 + (lane >> 2);
            const int c0 = (lane & 3) * 2;
            #pragma unroll
            for (int ks = 0; ks < 8; ++ks)
                #pragma unroll
                for (int q = 0; q < 4; ++q) {
                    int rr = r0 + ((q & 1) ? 8 : 0);
                    int cc = ks * 16 + c0 + ((q & 2) ? 8 : 0);
                    float2 v = *(const float2*)&conv_w[rr * CC + cc];
                    __half2 h = __floats2half2_rn(v.x, v.y);
                    Whi[ks][q] = *(uint32_t*)&h;
                }
        }
        const int rowL = krow0 + (lane >> 2);
        const int colL = nq * 32 + 2 * (lane & 3);

        for (int t = 0; t < NT; ++t) {
            BARSYNC(XC(t % 3));
            if (t >= 2) BARSYNC(LF(t & 1));
            const uint32_t xbase = sb + XBUF(t % 3);
            float* sLog = (float*)(sm + ((t & 1) ? OFF_LOG1 : OFF_LOG0));
            const uint32_t aB1 = xbase + (uint32_t)((lane & 15) * PBX) +
                                 (uint32_t)(((lane >> 4) << 3) * 2) +
                                 (uint32_t)(nq * 64);
            float accL[4][4];
            #pragma unroll
            for (int j = 0; j < 4; ++j)
                #pragma unroll
                for (int r = 0; r < 4; ++r) accL[j][r] = 0.0f;
            #pragma unroll
            for (int ks = 0; ks < 8; ++ks)
                #pragma unroll
                for (int nf = 0; nf < 2; ++nf) {
                    uint32_t a = aB1 + (uint32_t)(ks * 16 * PBX + nf * 32);
                    uint32_t Bhi[4];
                    ldm4t(Bhi, a);
                    mma_f16(accL[nf * 2 + 0], Whi[ks], &Bhi[0]);
                    mma_f16(accL[nf * 2 + 1], Whi[ks], &Bhi[2]);
                }
            #pragma unroll
            for (int j = 0; j < 4; ++j) {
                float* pp = sLog + rowL * PL + colL + j * 8;
                *(float2*)pp = make_float2(accL[j][0], accL[j][1]);
                *(float2*)(pp + 8 * PL) = make_float2(accL[j][2], accL[j][3]);
            }
            BARARR(LG(t & 1));
        }
    } else if (w < 16) {
        // ====== G2 group (warps 8-15): vlad += a @ x_hi^T ======
        const int g = w - 8;
        const int kq2 = g & 1;         // k-half
        const int cq = g >> 1;         // c-quarter
        const int kbase = kq2 * 32;
        const int cbase = cq * 32;
        float accV[2][4][4];
        float accS[2][4];
        #pragma unroll
        for (int i = 0; i < 2; ++i) {
            #pragma unroll
            for (int j = 0; j < 4; ++j)
                #pragma unroll
                for (int r = 0; r < 4; ++r) accV[i][j][r] = 0.0f;
            #pragma unroll
            for (int r = 0; r < 4; ++r) accS[i][r] = 0.0f;
        }

        for (int t = 0; t < NT; ++t) {
            BARSYNC(AIDB(t & 1));
            const uint32_t xbase = sb + XBUF(t % 3);
            const uint32_t awb = sb + ((t & 1) ? OFF_AWHI1 : OFF_AWHI0);
            const uint32_t aA2 = awb + (uint32_t)(((lane & 15)) * PBA) +
                                 (uint32_t)((lane >> 4) * 16);
            const uint32_t aB2 = xbase +
                                 (uint32_t)(((lane & 7) + ((lane >> 4) << 3)) * PBX) +
                                 (uint32_t)((lane & 8) * 2);
            #pragma unroll
            for (int ks = 0; ks < 4; ++ks) {
                uint32_t Ahi[2][4];
                #pragma unroll
                for (int mf = 0; mf < 2; ++mf)
                    ldm4(Ahi[mf],
                         aA2 + (uint32_t)((kbase + mf * 16) * PBA + ks * 32));
                #pragma unroll
                for (int cf = 0; cf < 2; ++cf) {
                    uint32_t a = aB2 + (uint32_t)((cbase + cf * 16) * PBX + ks * 32);
                    uint32_t Bhi[4];
                    ldm4(Bhi, a);
                    #pragma unroll
                    for (int mf = 0; mf < 2; ++mf)
                        #pragma unroll
                        for (int s = 0; s < 2; ++s)
                            mma_f16(accV[mf][cf * 2 + s], Ahi[mf], &Bhi[2 * s]);
                }
                if (cq == 3) {                     // asum via ones row c=128
                    uint32_t a = aB2 + (uint32_t)(128 * PBX + ks * 32);
                    uint32_t Bhi[4];
                    ldm4(Bhi, a);
                    #pragma unroll
                    for (int mf = 0; mf < 2; ++mf)
                        mma_f16(accS[mf], Ahi[mf], &Bhi[0]);
                }
            }
            BARARR(AWF(t & 1));
            BARARR(XFB(t % 3));
        }

        // ---- epilogue: write partial vlad + asum ----
        float* pv = g_pv + ((size_t)(stripe * BB + b)) * KK * CC;
        #pragma unroll
        for (int mf = 0; mf < 2; ++mf)
            #pragma unroll
            for (int j = 0; j < 4; ++j) {
                int k = kbase + mf * 16 + (lane >> 2);
                int c = cbase + j * 8 + 2 * (lane & 3);
                *(float2*)&pv[k * CC + c] =
                    make_float2(accV[mf][j][0], accV[mf][j][1]);
                *(float2*)&pv[(k + 8) * CC + c] =
                    make_float2(accV[mf][j][2], accV[mf][j][3]);
            }
        if (cq == 3 && (lane & 3) == 0) {
            float* pa = g_pa + (stripe * BB + b) * KK;
            #pragma unroll
            for (int mf = 0; mf < 2; ++mf) {
                int k = kbase + mf * 16 + (lane >> 2);
                pa[k] = accS[mf][0];
                pa[k + 8] = accS[mf][2];
            }
        }
    } else {
        // ====== scalar group (warps 16-23, 256 threads): conv + softmax =====
        const int st = tid - 512;       // 0..255
        const int q = st >> 6;          // softmax k-quarter (16 rows)
        const int col = st & 63;        // softmax column
        const int crow = st >> 1;       // conv channel row
        const int nh = st & 1;          // conv n-half
        float* sRed = smf + (OFF_RED >> 2);
        float* sBias = smf + (OFF_BIAS >> 2);

        auto conv_tile = [&](int tt) {
            const uint32_t dsthi = XBUF(tt % 3) +
                                   (uint32_t)(crow * PBX + nh * 64);
            const float4* src = (const float4*)(xb + (size_t)crow * NN +
                                                nbase + tt * TILE_N + nh * 32);
            #pragma unroll
            for (int j = 0; j < 8; ++j) {
                float4 v = src[j];
                __half2 h01 = __floats2half2_rn(v.x, v.y);
                __half2 h23 = __floats2half2_rn(v.z, v.w);
                *(uint2*)(sm + dsthi + j * 8) = make_uint2(
                    *(uint32_t*)&h01, *(uint32_t*)&h23);
            }
        };

        conv_tile(0);
        BARARR(XC(0));
        conv_tile(1);
        BARARR(XC(1));

        for (int t = 0; t < NT; ++t) {
            const int p = t & 1;
            BARSYNC(LG(p));
            float* sLog = (float*)(sm + (p ? OFF_LOG1 : OFF_LOG0));
            float l[16];
            float mx = 0.0f;
            #pragma unroll
            for (int i = 0; i < 16; ++i) {
                float lv = sLog[(q * 16 + i) * PL + col] + sBias[q * 16 + i];
                lv = fmaxf(lv, 0.0f);
                l[i] = lv;
                mx = fmaxf(mx, lv);
            }
            sRed[q * 64 + col] = mx;
            BARSYNC256(SBAR);
            mx = fmaxf(fmaxf(sRed[col], sRed[64 + col]),
                       fmaxf(sRed[128 + col], sRed[192 + col]));
            float ssum = 0.0f;
            #pragma unroll
            for (int i = 0; i < 16; ++i) {
                float e = fast_exp_neg(l[i] - mx);
                l[i] = e;
                ssum += e;
            }
            BARARR(LF(p));                 // l[] consumed -> LOG free
            sRed[256 + q * 64 + col] = ssum;
            BARSYNC256(SBAR);
            float rinv = 1.0f / (sRed[256 + col] + sRed[320 + col] +
                                 sRed[384 + col] + sRed[448 + col]);
            if (t >= 2) BARSYNC(AWF(p));   // G2(t-2) done with AW[p]
            const uint32_t awb = (p ? OFF_AWHI1 : OFF_AWHI0);
            #pragma unroll
            for (int i = 0; i < 16; ++i) {
                float a = l[i] * rinv;
                uint32_t off = (uint32_t)((q * 16 + i) * PA + col) * 2;
                *(uint16_t*)(sm + awb + off) =
                    __half_as_ushort(__float2half_rn(a));
            }
            BARARR(AIDB(p));
            if (t + 2 < NT) {
                if (t >= 1) BARSYNC(XFB((t + 2) % 3));  // G2(t-1) freed slot
                conv_tile(t + 2);
                BARARR(XC((t + 2) % 3));
            }
        }
    }
}

// ---------------- kernel 2: split-K reduce + centroid + intra-normalize -----
__global__ void nv_reduce_kernel(const float* __restrict__ centroids,
                                 float* __restrict__ out) {
    const int k = blockIdx.x, b = blockIdx.y, c = threadIdx.x;  // 128 threads
    float v = 0.0f;
    #pragma unroll
    for (int s = 0; s < STRIPES; s++)
        v += g_pv[(((size_t)s * BB + b) * KK + k) * CC + c];
    float as = 0.0f;
    #pragma unroll
    for (int s = 0; s < STRIPES; s++)
        as += g_pa[(s * BB + b) * KK + k];
    v -= as * centroids[k * CC + c];

    float ss = v * v;
    #pragma unroll
    for (int o = 16; o > 0; o >>= 1)
        ss += __shfl_xor_sync(0xffffffffu, ss, o);
    __shared__ float red[4];
    const int warp = c >> 5, lane = c & 31;
    if (lane == 0) red[warp] = ss;
    __syncthreads();
    float tot = red[0] + red[1] + red[2] + red[3];
    float inv = 1.0f / fmaxf(sqrtf(tot), 1e-12f);
    out[((size_t)b * KK + k) * CC + c] = v * inv;
    if (c == 0) g_rss[b * KK + k] = tot * inv * inv;
}

// ---------------- kernel 3: global L2 normalize per batch -------------------
__global__ void nv_gnorm_kernel(float* __restrict__ out) {
    const int b = blockIdx.y;
    __shared__ float ginv;
    if (threadIdx.x == 0) {
        float ss = 0.0f;
        #pragma unroll 8
        for (int k = 0; k < KK; k++) ss += g_rss[b * KK + k];
        ginv = 1.0f / fmaxf(sqrtf(ss), 1e-12f);
    }
    __syncthreads();
    int idx = b * KK * CC + blockIdx.x * 512 + threadIdx.x;
    out[idx] *= ginv;
}

// ---------------- launch -----------------------------------------------------
extern "C" void kernel_launch(void* const* d_in, const int* in_sizes, int n_in,
                              void* d_out, int out_size) {
    const float* x         = (const float*)d_in[0];  // (32,128,16384,1)
    const float* conv_w    = (const float*)d_in[1];  // (64,128)
    const float* conv_b    = (const float*)d_in[2];  // (64,)
    const float* centroids = (const float*)d_in[3];  // (64,128)
    float* out             = (float*)d_out;          // (32, 8192)

    cudaFuncSetAttribute((const void*)nv_df_kernel,
                         cudaFuncAttributeMaxDynamicSharedMemorySize, SMEM_BYTES);
    nv_df_kernel<<<dim3(STRIPES, BB), NTHREADS, SMEM_BYTES>>>(x, conv_w, conv_b);
    nv_reduce_kernel<<<dim3(KK, BB), 128>>>(centroids, out);
    nv_gnorm_kernel<<<dim3(16, BB), 512>>>(out);
}

// round 15
// speedup vs baseline: 1.0289x; 1.0289x over previous
#include <cuda_runtime.h>
#include <cuda_fp16.h>
#include <stdint.h>

// ---------------- problem constants ----------------
#define BB 32
#define CC 128
#define NN 16384
#define KK 64
#define TILE_N 128
#define STRIPES 4
#define NT ((NN / STRIPES) / TILE_N)   // 32 tiles per CTA
#define NTHREADS 384

// ---------------- smem layout ----------------
#define PX  136      // x tile pitch (elems); 272 B rows (odd 16B -> conflict-free)
#define PBX 272
#define PA  136
#define PBA 272
#define PL  132      // logits pitch (fp32)

#define XBUF(i)   ((uint32_t)(i) * 39168u)   // X ring (fp16), 2 deep, 144 rows
#define OFF_LOG0  78336u     // [64][132] fp32
#define OFF_LOG1  112128u
#define OFF_AW0   145920u    // [64][136] fp16
#define OFF_AW1   163328u
#define OFF_BIAS  180736u    // 64 fp32
#define SMEM_BYTES 181248u

// ---------------- named barrier ids ----------------
#define XC(s)   (1 + (s))    // conv(t) done -> G1 may read X[t%2]
#define XFB(s)  (3 + (s))    // G2(t) done  -> conv(t+2) may write X[t%2]
#define LG(p)   (5 + (p))    // G1(t) done  -> softmax may read LOG[t%2]
#define LF(p)   (7 + (p))    // softmax(t) read LOG -> G1(t+2) may write
#define AIDB(p) (9 + (p))    // softmax(t) done -> G2 may read AW[t%2]
#define AWF(p)  (11 + (p))   // G2(t) read AW[t%2] -> softmax(t+2) may write

#define BARSYNC(id)    asm volatile("bar.sync %0, 256;"   :: "r"(id) : "memory")
#define BARARR(id)     asm volatile("bar.arrive %0, 256;" :: "r"(id) : "memory")

// ---------------- scratch (deterministic split-K, no atomics) ---------------
__device__ float g_pv[(size_t)STRIPES * BB * KK * CC];
__device__ float g_pa[STRIPES * BB * KK];
__device__ float g_rss[BB * KK];

// ---------------- helpers ----------------
__device__ __forceinline__ uint32_t smem_u32(const void* p) {
    uint32_t a;
    asm("{ .reg .u64 t; cvta.to.shared.u64 t, %1; cvt.u32.u64 %0, t; }"
        : "=r"(a) : "l"(p));
    return a;
}
__device__ __forceinline__ void ldm4(uint32_t* r, uint32_t a) {
    asm volatile("ldmatrix.sync.aligned.m8n8.x4.shared.b16 {%0,%1,%2,%3}, [%4];"
                 : "=r"(r[0]), "=r"(r[1]), "=r"(r[2]), "=r"(r[3]) : "r"(a));
}
__device__ __forceinline__ void ldm4t(uint32_t* r, uint32_t a) {
    asm volatile("ldmatrix.sync.aligned.m8n8.x4.trans.shared.b16 {%0,%1,%2,%3}, [%4];"
                 : "=r"(r[0]), "=r"(r[1]), "=r"(r[2]), "=r"(r[3]) : "r"(a));
}
__device__ __forceinline__ void mma_f16(float* d, const uint32_t* a, const uint32_t* b2) {
    asm volatile("mma.sync.aligned.m16n8k16.row.col.f32.f16.f16.f32 "
                 "{%0,%1,%2,%3}, {%4,%5,%6,%7}, {%8,%9}, {%0,%1,%2,%3};"
                 : "+f"(d[0]), "+f"(d[1]), "+f"(d[2]), "+f"(d[3])
                 : "r"(a[0]), "r"(a[1]), "r"(a[2]), "r"(a[3]), "r"(b2[0]), "r"(b2[1]));
}

// fast exp for v <= 0: pure FFMA/ALU, rel err ~2.4e-6
__device__ __forceinline__ float fast_exp_neg(float v) {
    float t = v * 1.4426950408889634f;
    t = fmaxf(t, -30.0f);
    float r  = t + 12582912.0f;
    float fi = r - 12582912.0f;
    float f  = t - fi;
    float p  = 0.0013333558146428443f;
    p = fmaf(p, f, 0.009618129107628477f);
    p = fmaf(p, f, 0.05550410866482158f);
    p = fmaf(p, f, 0.2402265069591007f);
    p = fmaf(p, f, 0.6931471805599453f);
    p = fmaf(p, f, 1.0f);
    int ei = (int)fi;
    return __int_as_float(__float_as_int(p) + (ei << 23));
}

// ---------------- dataflow-pipelined fused kernel (TILE_N=128) --------------
__global__ __launch_bounds__(NTHREADS, 1)
void nv_df_kernel(const float* __restrict__ x,
                  const float* __restrict__ conv_w,
                  const float* __restrict__ conv_b) {
    extern __shared__ char sm[];
    const uint32_t sb = smem_u32(sm);
    float* smf = (float*)sm;
    const int tid = threadIdx.x;
    const int lane = tid & 31;
    const int w = tid >> 5;
    const int b = blockIdx.y, stripe = blockIdx.x;

    // ---- init: bias + ones rows (128) / zero rows (129..143), both buffers --
    if (tid < KK) smf[(OFF_BIAS >> 2) + tid] = conv_b[tid];
    for (int i = tid; i < 16 * PX; i += NTHREADS) {
        int r = 128 + i / PX, c = i % PX;
        uint16_t hv = (r == 128 && c < TILE_N) ? (uint16_t)0x3C00 : (uint16_t)0;
        uint32_t o = (uint32_t)(r * PX + c) * 2;
        *(uint16_t*)(sm + XBUF(0) + o) = hv;
        *(uint16_t*)(sm + XBUF(1) + o) = hv;
    }
    __syncthreads();

    const float* xb = x + (size_t)b * CC * NN;
    const int nbase = stripe * (NN / STRIPES);

    if (w < 4) {
        // ====== G1 group (warps 0-3): logits = Whi @ x_hi ======
        const int krow0 = w * 16;
        uint32_t Whi[8][4];
        {
            const int r0 = krow0 + (lane >> 2);
            const int c0 = (lane & 3) * 2;
            #pragma unroll
            for (int ks = 0; ks < 8; ++ks)
                #pragma unroll
                for (int q = 0; q < 4; ++q) {
                    int rr = r0 + ((q & 1) ? 8 : 0);
                    int cc = ks * 16 + c0 + ((q & 2) ? 8 : 0);
                    float2 v = *(const float2*)&conv_w[rr * CC + cc];
                    __half2 h = __floats2half2_rn(v.x, v.y);
                    Whi[ks][q] = *(uint32_t*)&h;
                }
        }
        const int rowL = krow0 + (lane >> 2);
        const int colL = 2 * (lane & 3);

        for (int t = 0; t < NT; ++t) {
            BARSYNC(XC(t & 1));
            if (t >= 2) BARSYNC(LF(t & 1));
            const uint32_t xbase = sb + XBUF(t & 1);
            float* sLog = (float*)(sm + ((t & 1) ? OFF_LOG1 : OFF_LOG0));
            const uint32_t aB1 = xbase + (uint32_t)((lane & 15) * PBX) +
                                 (uint32_t)(((lane >> 4) << 3) * 2);
            float accL[16][4];
            #pragma unroll
            for (int j = 0; j < 16; ++j)
                #pragma unroll
                for (int r = 0; r < 4; ++r) accL[j][r] = 0.0f;
            #pragma unroll
            for (int ks = 0; ks < 8; ++ks)
                #pragma unroll
                for (int nf = 0; nf < 8; ++nf) {
                    uint32_t a = aB1 + (uint32_t)(ks * 16 * PBX + nf * 32);
                    uint32_t Bhi[4];
                    ldm4t(Bhi, a);
                    mma_f16(accL[nf * 2 + 0], Whi[ks], &Bhi[0]);
                    mma_f16(accL[nf * 2 + 1], Whi[ks], &Bhi[2]);
                }
            #pragma unroll
            for (int j = 0; j < 16; ++j) {
                float* pp = sLog + rowL * PL + colL + j * 8;
                *(float2*)pp = make_float2(accL[j][0], accL[j][1]);
                *(float2*)(pp + 8 * PL) = make_float2(accL[j][2], accL[j][3]);
            }
            BARARR(LG(t & 1));
        }
    } else if (w < 8) {
        // ====== G2 group (warps 4-7): vlad += a @ x_hi^T ======
        const int g2w = w - 4;
        const int cbase = g2w * 32;
        float accV[4][4][4];
        float accS[4][4];
        #pragma unroll
        for (int i = 0; i < 4; ++i) {
            #pragma unroll
            for (int j = 0; j < 4; ++j)
                #pragma unroll
                for (int r = 0; r < 4; ++r) accV[i][j][r] = 0.0f;
            #pragma unroll
            for (int r = 0; r < 4; ++r) accS[i][r] = 0.0f;
        }

        for (int t = 0; t < NT; ++t) {
            BARSYNC(AIDB(t & 1));
            const uint32_t xbase = sb + XBUF(t & 1);
            const uint32_t awb = sb + ((t & 1) ? OFF_AW1 : OFF_AW0);
            const uint32_t aA2 = awb + (uint32_t)(((lane & 15)) * PBA) +
                                 (uint32_t)((lane >> 4) * 16);
            const uint32_t aB2 = xbase +
                                 (uint32_t)(((lane & 7) + ((lane >> 4) << 3)) * PBX) +
                                 (uint32_t)((lane & 8) * 2);
            #pragma unroll
            for (int ks = 0; ks < 8; ++ks) {
                uint32_t Ahi[4][4];
                #pragma unroll
                for (int mf = 0; mf < 4; ++mf)
                    ldm4(Ahi[mf], aA2 + (uint32_t)(mf * 16 * PBA + ks * 32));
                #pragma unroll
                for (int cf = 0; cf < 2; ++cf) {
                    uint32_t a = aB2 + (uint32_t)((cbase + cf * 16) * PBX + ks * 32);
                    uint32_t Bhi[4];
                    ldm4(Bhi, a);
                    #pragma unroll
                    for (int mf = 0; mf < 4; ++mf)
                        #pragma unroll
                        for (int s = 0; s < 2; ++s)
                            mma_f16(accV[mf][cf * 2 + s], Ahi[mf], &Bhi[2 * s]);
                }
                if (g2w == 3) {                    // asum via ones row c=128
                    uint32_t a = aB2 + (uint32_t)(128 * PBX + ks * 32);
                    uint32_t Bhi[4];
                    ldm4(Bhi, a);
                    #pragma unroll
                    for (int mf = 0; mf < 4; ++mf)
                        mma_f16(accS[mf], Ahi[mf], &Bhi[0]);
                }
            }
            BARARR(AWF(t & 1));
            BARARR(XFB(t & 1));
        }

        // ---- epilogue: write partial vlad + asum ----
        float* pv = g_pv + ((size_t)(stripe * BB + b)) * KK * CC;
        #pragma unroll
        for (int mf = 0; mf < 4; ++mf)
            #pragma unroll
            for (int j = 0; j < 4; ++j) {
                int k = mf * 16 + (lane >> 2);
                int c = cbase + j * 8 + 2 * (lane & 3);
                *(float2*)&pv[k * CC + c] =
                    make_float2(accV[mf][j][0], accV[mf][j][1]);
                *(float2*)&pv[(k + 8) * CC + c] =
                    make_float2(accV[mf][j][2], accV[mf][j][3]);
            }
        if (g2w == 3 && (lane & 3) == 0) {
            float* pa = g_pa + (stripe * BB + b) * KK;
            #pragma unroll
            for (int mf = 0; mf < 4; ++mf) {
                int k = mf * 16 + (lane >> 2);
                pa[k] = accS[mf][0];
                pa[k + 8] = accS[mf][2];
            }
        }
    } else {
        // ====== scalar group (warps 8-11): conv + thread-local softmax ======
        const int st = tid - 256;       // 0..127 (column / channel row)
        float* sBias = smf + (OFF_BIAS >> 2);

        auto conv_tile = [&](int tt) {
            const uint32_t dst = XBUF(tt & 1) + (uint32_t)(st * PBX);
            const float4* src =
                (const float4*)(xb + (size_t)st * NN + nbase + tt * TILE_N);
            #pragma unroll
            for (int j = 0; j < 32; ++j) {
                float4 v = src[j];
                __half2 h01 = __floats2half2_rn(v.x, v.y);
                __half2 h23 = __floats2half2_rn(v.z, v.w);
                *(uint2*)(sm + dst + j * 8) = make_uint2(
                    *(uint32_t*)&h01, *(uint32_t*)&h23);
            }
        };

        conv_tile(0);
        BARARR(XC(0));

        for (int t = 0; t < NT; ++t) {
            const int p = t & 1;
            BARSYNC(LG(p));
            float* sLog = (float*)(sm + (p ? OFF_LOG1 : OFF_LOG0));
            // thread-local softmax over all 64 k for column st
            float l[64];
            float mx = 0.0f;
            #pragma unroll
            for (int i = 0; i < 64; ++i) {
                float lv = sLog[i * PL + st] + sBias[i];
                lv = fmaxf(lv, 0.0f);
                l[i] = lv;
                mx = fmaxf(mx, lv);
            }
            float ssum = 0.0f;
            #pragma unroll
            for (int i = 0; i < 64; ++i) {
                float e = fast_exp_neg(l[i] - mx);
                l[i] = e;
                ssum += e;
            }
            BARARR(LF(p));                 // LOG consumed -> G1(t+2) may write
            float rinv = 1.0f / ssum;      // ssum >= 1
            if (t >= 2) BARSYNC(AWF(p));   // G2(t-2) done with AW[p]
            const uint32_t awb = (p ? OFF_AW1 : OFF_AW0);
            #pragma unroll
            for (int i = 0; i < 64; ++i) {
                float a = l[i] * rinv;
                uint32_t off = (uint32_t)(i * PA + st) * 2;
                *(uint16_t*)(sm + awb + off) =
                    __half_as_ushort(__float2half_rn(a));
            }
            BARARR(AIDB(p));
            if (t + 1 < NT) {
                if (t >= 1) BARSYNC(XFB((t + 1) & 1));  // G2(t-1) freed slot
                conv_tile(t + 1);
                BARARR(XC((t + 1) & 1));
            }
        }
    }
}

// ---------------- kernel 2: split-K reduce + centroid + intra-normalize -----
__global__ void nv_reduce_kernel(const float* __restrict__ centroids,
                                 float* __restrict__ out) {
    const int k = blockIdx.x, b = blockIdx.y, c = threadIdx.x;  // 128 threads
    float v = 0.0f;
    #pragma unroll
    for (int s = 0; s < STRIPES; s++)
        v += g_pv[(((size_t)s * BB + b) * KK + k) * CC + c];
    float as = 0.0f;
    #pragma unroll
    for (int s = 0; s < STRIPES; s++)
        as += g_pa[(s * BB + b) * KK + k];
    v -= as * centroids[k * CC + c];

    float ss = v * v;
    #pragma unroll
    for (int o = 16; o > 0; o >>= 1)
        ss += __shfl_xor_sync(0xffffffffu, ss, o);
    __shared__ float red[4];
    const int warp = c >> 5, lane = c & 31;
    if (lane == 0) red[warp] = ss;
    __syncthreads();
    float tot = red[0] + red[1] + red[2] + red[3];
    float inv = 1.0f / fmaxf(sqrtf(tot), 1e-12f);
    out[((size_t)b * KK + k) * CC + c] = v * inv;
    if (c == 0) g_rss[b * KK + k] = tot * inv * inv;
}

// ---------------- kernel 3: global L2 normalize per batch -------------------
__global__ void nv_gnorm_kernel(float* __restrict__ out) {
    const int b = blockIdx.y;
    __shared__ float ginv;
    if (threadIdx.x == 0) {
        float ss = 0.0f;
        #pragma unroll 8
        for (int k = 0; k < KK; k++) ss += g_rss[b * KK + k];
        ginv = 1.0f / fmaxf(sqrtf(ss), 1e-12f);
    }
    __syncthreads();
    int idx = b * KK * CC + blockIdx.x * 512 + threadIdx.x;
    out[idx] *= ginv;
}

// ---------------- launch -----------------------------------------------------
extern "C" void kernel_launch(void* const* d_in, const int* in_sizes, int n_in,
                              void* d_out, int out_size) {
    const float* x         = (const float*)d_in[0];  // (32,128,16384,1)
    const float* conv_w    = (const float*)d_in[1];  // (64,128)
    const float* conv_b    = (const float*)d_in[2];  // (64,)
    const float* centroids = (const float*)d_in[3];  // (64,128)
    float* out             = (float*)d_out;          // (32, 8192)

    cudaFuncSetAttribute((const void*)nv_df_kernel,
                         cudaFuncAttributeMaxDynamicSharedMemorySize, SMEM_BYTES);
    nv_df_kernel<<<dim3(STRIPES, BB), NTHREADS, SMEM_BYTES>>>(x, conv_w, conv_b);
    nv_reduce_kernel<<<dim3(KK, BB), 128>>>(centroids, out);
    nv_gnorm_kernel<<<dim3(16, BB), 512>>>(out);
}

// round 16
// speedup vs baseline: 1.0958x; 1.0650x over previous
#include <cuda_runtime.h>
#include <cuda_fp16.h>
#include <stdint.h>

// ---------------- problem constants ----------------
#define BB 32
#define CC 128
#define NN 16384
#define KK 64
#define TILE_N 64
#define STRIPES 4
#define NT ((NN / STRIPES) / TILE_N)   // 64 tiles per CTA
#define NTHREADS 384

// ---------------- smem layout ----------------
#define PX  72       // x tile pitch (elems); 144 B rows
#define PBX 144
#define PA  72
#define PBA 144
#define PL  68       // logits pitch (fp32)

#define XBUF(i)   ((uint32_t)(i) * 20736u)   // X ring (fp16 hi only), 3 deep
#define OFF_LOG0  62208u     // [64][68] fp32
#define OFF_LOG1  79616u
#define OFF_AWHI0 97024u     // [64][72] fp16
#define OFF_AWHI1 106240u
#define OFF_BIAS  115456u    // 64 fp32
#define OFF_RED   115712u    // 256 fp32
#define SMEM_BYTES 116736u

// ---------------- named barrier ids ----------------
#define XC(s)  (1 + (s))     // conv(t) done -> G1 may read X[t%3]
#define XFB(s) (4 + (s))     // G2(t) done  -> conv(t+3) may write X[t%3]
#define LG(p)  (7 + (p))     // G1(t) done  -> softmax may read LOG[t%2]
#define LF(p)  (9 + (p))     // softmax(t) read LOG -> G1(t+2) may write
#define AIDB(p) (11 + (p))   // softmax(t) done -> G2 may read AW[t%2]
#define AWF(p) (13 + (p))    // G2(t) read AW[t%2] -> softmax(t+2) may write
#define SBAR   15            // scalar-internal (128)

#define BARSYNC(id)    asm volatile("bar.sync %0, 256;"   :: "r"(id) : "memory")
#define BARARR(id)     asm volatile("bar.arrive %0, 256;" :: "r"(id) : "memory")
#define BARSYNC128(id) asm volatile("bar.sync %0, 128;"   :: "r"(id) : "memory")

// ---------------- scratch (deterministic split-K, no atomics) ---------------
__device__ float g_pv[(size_t)STRIPES * BB * KK * CC];
__device__ float g_pa[STRIPES * BB * KK];
__device__ float g_rss[BB * KK];

// ---------------- helpers ----------------
__device__ __forceinline__ uint32_t smem_u32(const void* p) {
    uint32_t a;
    asm("{ .reg .u64 t; cvta.to.shared.u64 t, %1; cvt.u32.u64 %0, t; }"
        : "=r"(a) : "l"(p));
    return a;
}
__device__ __forceinline__ void ldm4(uint32_t* r, uint32_t a) {
    asm volatile("ldmatrix.sync.aligned.m8n8.x4.shared.b16 {%0,%1,%2,%3}, [%4];"
                 : "=r"(r[0]), "=r"(r[1]), "=r"(r[2]), "=r"(r[3]) : "r"(a));
}
__device__ __forceinline__ void ldm4t(uint32_t* r, uint32_t a) {
    asm volatile("ldmatrix.sync.aligned.m8n8.x4.trans.shared.b16 {%0,%1,%2,%3}, [%4];"
                 : "=r"(r[0]), "=r"(r[1]), "=r"(r[2]), "=r"(r[3]) : "r"(a));
}
__device__ __forceinline__ void mma_f16(float* d, const uint32_t* a, const uint32_t* b2) {
    asm volatile("mma.sync.aligned.m16n8k16.row.col.f32.f16.f16.f32 "
                 "{%0,%1,%2,%3}, {%4,%5,%6,%7}, {%8,%9}, {%0,%1,%2,%3};"
                 : "+f"(d[0]), "+f"(d[1]), "+f"(d[2]), "+f"(d[3])
                 : "r"(a[0]), "r"(a[1]), "r"(a[2]), "r"(a[3]), "r"(b2[0]), "r"(b2[1]));
}

// fast exp for v <= 0: pure FFMA/ALU, rel err ~2.4e-6
__device__ __forceinline__ float fast_exp_neg(float v) {
    float t = v * 1.4426950408889634f;
    t = fmaxf(t, -30.0f);
    float r  = t + 12582912.0f;
    float fi = r - 12582912.0f;
    float f  = t - fi;
    float p  = 0.0013333558146428443f;
    p = fmaf(p, f, 0.009618129107628477f);
    p = fmaf(p, f, 0.05550410866482158f);
    p = fmaf(p, f, 0.2402265069591007f);
    p = fmaf(p, f, 0.6931471805599453f);
    p = fmaf(p, f, 1.0f);
    int ei = (int)fi;
    return __int_as_float(__float_as_int(p) + (ei << 23));
}

// ---------------- dataflow-pipelined fused kernel ----------------
__global__ __launch_bounds__(NTHREADS, 1)
void nv_df_kernel(const float* __restrict__ x,
                  const float* __restrict__ conv_w,
                  const float* __restrict__ conv_b) {
    extern __shared__ char sm[];
    const uint32_t sb = smem_u32(sm);
    float* smf = (float*)sm;
    const int tid = threadIdx.x;
    const int lane = tid & 31;
    const int w = tid >> 5;
    const int b = blockIdx.y, stripe = blockIdx.x;

    // ---- init: bias + ones rows in all 3 X buffers ----
    if (tid < KK) smf[(OFF_BIAS >> 2) + tid] = conv_b[tid];
    for (int i = tid; i < 16 * PX; i += NTHREADS) {   // rows 128..143
        int r = 128 + i / PX, c = i % PX;
        uint16_t hv = (r == 128) ? (uint16_t)0x3C00 : (uint16_t)0;   // fp16 1.0
        uint32_t o = (uint32_t)(r * PX + c) * 2;
        #pragma unroll
        for (int bu = 0; bu < 3; ++bu)
            *(uint16_t*)(sm + XBUF(bu) + o) = hv;
    }
    __syncthreads();

    const float* xb = x + (size_t)b * CC * NN;
    const int nbase = stripe * (NN / STRIPES);

    if (w < 4) {
        // ====== G1 group (warps 0-3): logits = Whi @ x_hi ======
        // warp -> (k-half kq = w&1, n-half nq = w>>1): W k32 slice in regs,
        // each warp reads only its n-half of X (2x redundancy vs 4x before)
        const int kq = w & 1;
        const int nq = (w >> 1) & 1;
        const int krow0 = kq * 32;
        uint32_t Whi[8][2][4];
        {
            const int r0 = krow0 + (lane >> 2);
            const int c0 = (lane & 3) * 2;
            #pragma unroll
            for (int ks = 0; ks < 8; ++ks)
                #pragma unroll
                for (int mf = 0; mf < 2; ++mf)
                    #pragma unroll
                    for (int q = 0; q < 4; ++q) {
                        int rr = r0 + mf * 16 + ((q & 1) ? 8 : 0);
                        int cc = ks * 16 + c0 + ((q & 2) ? 8 : 0);
                        float2 v = *(const float2*)&conv_w[rr * CC + cc];
                        __half2 h = __floats2half2_rn(v.x, v.y);
                        Whi[ks][mf][q] = *(uint32_t*)&h;
                    }
        }
        const int rowL = krow0 + (lane >> 2);
        const int colL = nq * 32 + 2 * (lane & 3);

        for (int t = 0; t < NT; ++t) {
            BARSYNC(XC(t % 3));
            if (t >= 2) BARSYNC(LF(t & 1));
            const uint32_t xbase = sb + XBUF(t % 3);
            float* sLog = (float*)(sm + ((t & 1) ? OFF_LOG1 : OFF_LOG0));
            const uint32_t aB1 = xbase + (uint32_t)((lane & 15) * PBX) +
                                 (uint32_t)(((lane >> 4) << 3) * 2) +
                                 (uint32_t)(nq * 64);
            float accL[2][4][4];
            #pragma unroll
            for (int i = 0; i < 2; ++i)
                #pragma unroll
                for (int j = 0; j < 4; ++j)
                    #pragma unroll
                    for (int r = 0; r < 4; ++r) accL[i][j][r] = 0.0f;
            #pragma unroll
            for (int ks = 0; ks < 8; ++ks)
                #pragma unroll
                for (int nf = 0; nf < 2; ++nf) {
                    uint32_t a = aB1 + (uint32_t)(ks * 16 * PBX + nf * 32);
                    uint32_t Bhi[4];
                    ldm4t(Bhi, a);
                    #pragma unroll
                    for (int mf = 0; mf < 2; ++mf) {
                        mma_f16(accL[mf][nf * 2 + 0], Whi[ks][mf], &Bhi[0]);
                        mma_f16(accL[mf][nf * 2 + 1], Whi[ks][mf], &Bhi[2]);
                    }
                }
            #pragma unroll
            for (int mf = 0; mf < 2; ++mf)
                #pragma unroll
                for (int nf = 0; nf < 4; ++nf) {
                    float* pp = sLog + (rowL + mf * 16) * PL + colL + nf * 8;
                    *(float2*)pp = make_float2(accL[mf][nf][0], accL[mf][nf][1]);
                    *(float2*)(pp + 8 * PL) =
                        make_float2(accL[mf][nf][2], accL[mf][nf][3]);
                }
            BARARR(LG(t & 1));
        }
    } else if (w < 8) {
        // ====== G2 group (warps 4-7): vlad += a @ x_hi^T (1 product) ======
        const int g2w = w - 4;
        const int cbase = g2w * 32;
        float accV[4][4][4];
        float accS[4][4];
        #pragma unroll
        for (int i = 0; i < 4; ++i) {
            #pragma unroll
            for (int j = 0; j < 4; ++j)
                #pragma unroll
                for (int r = 0; r < 4; ++r) accV[i][j][r] = 0.0f;
            #pragma unroll
            for (int r = 0; r < 4; ++r) accS[i][r] = 0.0f;
        }

        for (int t = 0; t < NT; ++t) {
            BARSYNC(AIDB(t & 1));
            const uint32_t xbase = sb + XBUF(t % 3);
            const uint32_t awb = sb + ((t & 1) ? OFF_AWHI1 : OFF_AWHI0);
            const uint32_t aA2 = awb + (uint32_t)(((lane & 15)) * PBA) +
                                 (uint32_t)((lane >> 4) * 16);
            const uint32_t aB2 = xbase +
                                 (uint32_t)(((lane & 7) + ((lane >> 4) << 3)) * PBX) +
                                 (uint32_t)((lane & 8) * 2);
            #pragma unroll
            for (int ks = 0; ks < 4; ++ks) {
                uint32_t Ahi[4][4];
                #pragma unroll
                for (int mf = 0; mf < 4; ++mf)
                    ldm4(Ahi[mf], aA2 + (uint32_t)(mf * 16 * PBA + ks * 32));
                #pragma unroll
                for (int cf = 0; cf < 2; ++cf) {
                    uint32_t a = aB2 + (uint32_t)((cbase + cf * 16) * PBX + ks * 32);
                    uint32_t Bhi[4];
                    ldm4(Bhi, a);
                    #pragma unroll
                    for (int mf = 0; mf < 4; ++mf)
                        #pragma unroll
                        for (int s = 0; s < 2; ++s)
                            mma_f16(accV[mf][cf * 2 + s], Ahi[mf], &Bhi[2 * s]);
                }
                if (g2w == 3) {                    // asum via ones row c=128
                    uint32_t a = aB2 + (uint32_t)(128 * PBX + ks * 32);
                    uint32_t Bhi[4];
                    ldm4(Bhi, a);
                    #pragma unroll
                    for (int mf = 0; mf < 4; ++mf)
                        mma_f16(accS[mf], Ahi[mf], &Bhi[0]);
                }
            }
            BARARR(AWF(t & 1));
            BARARR(XFB(t % 3));
        }

        // ---- epilogue: write partial vlad + asum ----
        float* pv = g_pv + ((size_t)(stripe * BB + b)) * KK * CC;
        #pragma unroll
        for (int mf = 0; mf < 4; ++mf)
            #pragma unroll
            for (int j = 0; j < 4; ++j) {
                int k = mf * 16 + (lane >> 2);
                int c = cbase + j * 8 + 2 * (lane & 3);
                *(float2*)&pv[k * CC + c] =
                    make_float2(accV[mf][j][0], accV[mf][j][1]);
                *(float2*)&pv[(k + 8) * CC + c] =
                    make_float2(accV[mf][j][2], accV[mf][j][3]);
            }
        if (g2w == 3 && (lane & 3) == 0) {
            float* pa = g_pa + (stripe * BB + b) * KK;
            #pragma unroll
            for (int mf = 0; mf < 4; ++mf) {
                int k = mf * 16 + (lane >> 2);
                pa[k] = accS[mf][0];
                pa[k + 8] = accS[mf][2];
            }
        }
    } else {
        // ====== scalar group (warps 8-11): conv + softmax ======
        const int st = tid - 256;       // 0..127
        const int half_ = st >> 6;      // softmax k-half
        const int col = st & 63;        // softmax column
        float* sRed = smf + (OFF_RED >> 2);
        float* sBias = smf + (OFF_BIAS >> 2);

        auto conv_tile = [&](int tt) {
            const uint32_t dsthi = XBUF(tt % 3) + (uint32_t)(st * PBX);
            const float4* src =
                (const float4*)(xb + (size_t)st * NN + nbase + tt * TILE_N);
            #pragma unroll
            for (int j = 0; j < 16; ++j) {
                float4 v = src[j];
                __half2 h01 = __floats2half2_rn(v.x, v.y);
                __half2 h23 = __floats2half2_rn(v.z, v.w);
                *(uint2*)(sm + dsthi + j * 8) = make_uint2(
                    *(uint32_t*)&h01, *(uint32_t*)&h23);
            }
        };

        conv_tile(0);
        BARARR(XC(0));
        conv_tile(1);
        BARARR(XC(1));

        for (int t = 0; t < NT; ++t) {
            const int p = t & 1;
            BARSYNC(LG(p));
            float* sLog = (float*)(sm + (p ? OFF_LOG1 : OFF_LOG0));
            float l[32];
            float mx = 0.0f;
            #pragma unroll
            for (int i = 0; i < 32; ++i) {
                float lv = sLog[(half_ * 32 + i) * PL + col] + sBias[half_ * 32 + i];
                lv = fmaxf(lv, 0.0f);
                l[i] = lv;
                mx = fmaxf(mx, lv);
            }
            sRed[half_ * 64 + col] = mx;
            BARSYNC128(SBAR);
            mx = fmaxf(sRed[col], sRed[64 + col]);
            float ssum = 0.0f;
            #pragma unroll
            for (int i = 0; i < 32; ++i) {
                float e = fast_exp_neg(l[i] - mx);
                l[i] = e;
                ssum += e;
            }
            BARARR(LF(p));                 // l[] consumed -> LOG free
            sRed[128 + half_ * 64 + col] = ssum;
            BARSYNC128(SBAR);
            float rinv = 1.0f / (sRed[128 + col] + sRed[192 + col]);
            if (t >= 2) BARSYNC(AWF(p));   // G2(t-2) done with AW[p]
            const uint32_t awb = (p ? OFF_AWHI1 : OFF_AWHI0);
            #pragma unroll
            for (int i = 0; i < 32; ++i) {
                float a = l[i] * rinv;
                uint32_t off = (uint32_t)((half_ * 32 + i) * PA + col) * 2;
                *(uint16_t*)(sm + awb + off) =
                    __half_as_ushort(__float2half_rn(a));
            }
            BARARR(AIDB(p));
            if (t + 2 < NT) {
                if (t >= 1) BARSYNC(XFB((t + 2) % 3));  // G2(t-1) freed slot
                conv_tile(t + 2);
                BARARR(XC((t + 2) % 3));
            }
        }
    }
}

// ---------------- kernel 2: split-K reduce + centroid + intra-normalize -----
__global__ void nv_reduce_kernel(const float* __restrict__ centroids,
                                 float* __restrict__ out) {
    const int k = blockIdx.x, b = blockIdx.y, c = threadIdx.x;  // 128 threads
    float v = 0.0f;
    #pragma unroll
    for (int s = 0; s < STRIPES; s++)
        v += g_pv[(((size_t)s * BB + b) * KK + k) * CC + c];
    float as = 0.0f;
    #pragma unroll
    for (int s = 0; s < STRIPES; s++)
        as += g_pa[(s * BB + b) * KK + k];
    v -= as * centroids[k * CC + c];

    float ss = v * v;
    #pragma unroll
    for (int o = 16; o > 0; o >>= 1)
        ss += __shfl_xor_sync(0xffffffffu, ss, o);
    __shared__ float red[4];
    const int warp = c >> 5, lane = c & 31;
    if (lane == 0) red[warp] = ss;
    __syncthreads();
    float tot = red[0] + red[1] + red[2] + red[3];
    float inv = 1.0f / fmaxf(sqrtf(tot), 1e-12f);
    out[((size_t)b * KK + k) * CC + c] = v * inv;
    if (c == 0) g_rss[b * KK + k] = tot * inv * inv;
}

// ---------------- kernel 3: global L2 normalize per batch -------------------
__global__ void nv_gnorm_kernel(float* __restrict__ out) {
    const int b = blockIdx.y;
    __shared__ float ginv;
    if (threadIdx.x == 0) {
        float ss = 0.0f;
        #pragma unroll 8
        for (int k = 0; k < KK; k++) ss += g_rss[b * KK + k];
        ginv = 1.0f / fmaxf(sqrtf(ss), 1e-12f);
    }
    __syncthreads();
    int idx = b * KK * CC + blockIdx.x * 512 + threadIdx.x;
    out[idx] *= ginv;
}

// ---------------- launch -----------------------------------------------------
extern "C" void kernel_launch(void* const* d_in, const int* in_sizes, int n_in,
                              void* d_out, int out_size) {
    const float* x         = (const float*)d_in[0];  // (32,128,16384,1)
    const float* conv_w    = (const float*)d_in[1];  // (64,128)
    const float* conv_b    = (const float*)d_in[2];  // (64,)
    const float* centroids = (const float*)d_in[3];  // (64,128)
    float* out             = (float*)d_out;          // (32, 8192)

    cudaFuncSetAttribute((const void*)nv_df_kernel,
                         cudaFuncAttributeMaxDynamicSharedMemorySize, SMEM_BYTES);
    nv_df_kernel<<<dim3(STRIPES, BB), NTHREADS, SMEM_BYTES>>>(x, conv_w, conv_b);
    nv_reduce_kernel<<<dim3(KK, BB), 128>>>(centroids, out);
    nv_gnorm_kernel<<<dim3(16, BB), 512>>>(out);
}